// round 12
// baseline (speedup 1.0000x reference)
#include <cuda_runtime.h>

// ============================================================================
// MultinomialKLDivergenceLoss — FINAL kernel (GB300 / sm_103a), 127.1 us
//
// Pure streaming reduction: 819.2 MB read once at the chip's path-independent
// LTS throughput cap (6.41-6.46 TB/s achieved across all variants). Measured
// 99.8% of the achieved-bandwidth roofline (819.2 MB / 6.457 TB/s = 126.9 us).
//
// Validated design points (one bench round each):
//   - no MUFU: log(q)-log(p) via integer exponent extraction + Taylor-7
//     log1p on [-1/3,1/3]; fma/alu pipes only (rel_err 3e-7 vs 1e-3 tol).
//     This was the decisive optimization (naive logf => MUFU-bound ~1.5 ms).
//   - SPLITS=4 CTAs/row: measured optimum of drain-tail vs CTA-churn
//     (1:129.3  2:128.2  4:127.1  8:136.0 us).
//   - mask argmax(p_row)!=0  <=>  max(p_row) > p_row[0] (first-max semantics).
//   - single launch: cross-CTA row combine + global finalize via atomics that
//     self-re-arm (atomicExch) => deterministic under CUDA-graph replay.
// Tested-and-neutral (LTS cap is path-independent): cache hints, MLP batching,
// launch fusion, 128B-aligned segments. Tested-and-worse: 512-thr CTAs (reg
// occupancy), SPLITS=8 (churn).
// ============================================================================

static constexpr int VOCAB = 25000;
static constexpr int V4 = VOCAB / 4;       // 6250 float4 per row (row stride 100000 B, 16B aligned)
static constexpr int THREADS = 256;
static constexpr int SPLITS = 4;           // CTAs per row — measured optimum
static constexpr int QBASE = V4 / SPLITS;  // 1562
static constexpr int QREM  = V4 % SPLITS;  // 2 -> first 2 quarters get +1
static constexpr int MAX_ROWS = 8192;

// Per-row combine scratch + global finalize state. Zero-initialized at module
// load; every participant resets what it consumed (atomicExch), so each graph
// replay starts from the identical state.
__device__ float        g_row_sum[MAX_ROWS];
__device__ int          g_row_max[MAX_ROWS];   // int bits of positive float: order-preserving
__device__ unsigned int g_row_cnt[MAX_ROWS];
__device__ float        g_scratch = 0.0f;
__device__ unsigned int g_done    = 0u;

// log1p(f) for f in [-1/3, 1/3]:  f + f^2 * P(f), Taylor degree 7.
// Max abs error ~1.9e-5, far under the 1e-3 tolerance (measured rel_err ~3e-7).
__device__ __forceinline__ float log1p_poly(float f) {
    float p = 0.142857143f;               // 1/7
    p = fmaf(p, f, -0.166666667f);        // -1/6
    p = fmaf(p, f,  0.200000000f);        //  1/5
    p = fmaf(p, f, -0.250000000f);        // -1/4
    p = fmaf(p, f,  0.333333333f);        //  1/3
    p = fmaf(p, f, -0.500000000f);        // -1/2
    return fmaf(p, f * f, f);
}

// log(q) - log(p) without MUFU: integer exponent extraction centers the
// mantissa in [2/3, 4/3) (njuffa trick); exponents combine exactly in int.
__device__ __forceinline__ float log_ratio(float q, float p) {
    int iq = __float_as_int(q), ip = __float_as_int(p);
    int eq = (iq - 0x3f2aaaab) & 0xff800000;
    int ep = (ip - 0x3f2aaaab) & 0xff800000;
    float fq = __int_as_float(iq - eq) - 1.0f;
    float fp = __int_as_float(ip - ep) - 1.0f;
    float ed = (float)(eq - ep);          // exact: multiple of 2^23, fits int32
    return fmaf(ed, 8.26295788e-8f, log1p_poly(fq) - log1p_poly(fp));   // ln2/2^23
}

__device__ __forceinline__ void accum4(const float4& pv, const float4& qv,
                                       float& acc, float& vmax) {
    acc = fmaf(qv.x, log_ratio(qv.x, pv.x), acc);
    acc = fmaf(qv.y, log_ratio(qv.y, pv.y), acc);
    acc = fmaf(qv.z, log_ratio(qv.z, pv.z), acc);
    acc = fmaf(qv.w, log_ratio(qv.w, pv.w), acc);
    vmax = fmaxf(vmax, fmaxf(fmaxf(pv.x, pv.y), fmaxf(pv.z, pv.w)));
}

__global__ void __launch_bounds__(THREADS)
kl_kernel(const float* __restrict__ p, const float* __restrict__ q,
          float* __restrict__ out, float inv_rows, unsigned int nrows) {
    const int row = blockIdx.x >> 2;
    const int qtr = blockIdx.x & 3;
    const int tid = threadIdx.x;

    // Quarter bounds: first QREM quarters take QBASE+1 float4s.
    const int qbeg = qtr * QBASE + (qtr < QREM ? qtr : QREM);
    const int qcnt = QBASE + (qtr < QREM ? 1 : 0);

    const size_t rbase = (size_t)row * VOCAB;
    const float4* p4 = reinterpret_cast<const float4*>(p + rbase) + qbeg;
    const float4* q4 = reinterpret_cast<const float4*>(q + rbase) + qbeg;

    float acc  = 0.0f;
    float vmax = 0.0f;   // inputs strictly positive; 0 bits == int 0 (scratch init)

    for (int idx = tid; idx < qcnt; idx += THREADS) {
        float4 pv = __ldcs(p4 + idx);
        float4 qv = __ldcs(q4 + idx);
        accum4(pv, qv, acc, vmax);
    }

    // intra-warp reduction
    #pragma unroll
    for (int o = 16; o; o >>= 1) {
        acc  += __shfl_xor_sync(0xffffffffu, acc, o);
        vmax  = fmaxf(vmax, __shfl_xor_sync(0xffffffffu, vmax, o));
    }

    __shared__ float s_acc[THREADS / 32];
    __shared__ float s_max[THREADS / 32];
    const int wid = tid >> 5;
    const int lid = tid & 31;
    if (lid == 0) { s_acc[wid] = acc; s_max[wid] = vmax; }
    __syncthreads();

    if (tid == 0) {
        float a = 0.0f, m = 0.0f;
        #pragma unroll
        for (int w = 0; w < THREADS / 32; w++) {
            a += s_acc[w];
            m  = fmaxf(m, s_max[w]);
        }

        // Combine the SPLITS partials for this row (mask needs full-row max).
        atomicAdd(&g_row_sum[row], a);
        atomicMax(&g_row_max[row], __float_as_int(m));  // positive floats: int order == float order
        __threadfence();
        unsigned int arrived = atomicAdd(&g_row_cnt[row], 1u);
        if (arrived == SPLITS - 1u) {
            // Last quarter to arrive finalizes the row. atomicExch reads the
            // combined values coherently from L2 AND re-arms the slots.
            float rsum = atomicExch(&g_row_sum[row], 0.0f);
            int   rmax = atomicExch(&g_row_max[row], 0);
            atomicExch(&g_row_cnt[row], 0u);

            // argmax(p_row) != 0  <=>  max(p_row) > p_row[0]
            // (argmax returns the FIRST max; a tie at index 0 means argmax==0)
            float p0 = __ldg(p + rbase);
            if (__int_as_float(rmax) > p0) atomicAdd(&g_scratch, rsum * inv_rows);

            __threadfence();
            unsigned int done = atomicAdd(&g_done, 1u);
            if (done == nrows - 1u) {
                out[0] = atomicExch(&g_scratch, 0.0f);
                atomicExch(&g_done, 0u);
            }
        }
    }
}

extern "C" void kernel_launch(void* const* d_in, const int* in_sizes, int n_in,
                              void* d_out, int out_size) {
    const float* p = (const float*)d_in[0];
    const float* q = (const float*)d_in[1];
    float* out = (float*)d_out;

    const int total = in_sizes[0];      // D0*D1*V = 102,400,000
    const int rows  = total / VOCAB;    // 4096

    kl_kernel<<<rows * SPLITS, THREADS>>>(p, q, out, 1.0f / (float)rows,
                                          (unsigned int)rows);
}

// round 13
// speedup vs baseline: 1.0141x; 1.0141x over previous
#include <cuda_runtime.h>

// ============================================================================
// MultinomialKLDivergenceLoss — FINAL kernel (GB300 / sm_103a)
//
// Pure streaming reduction: 819.2 MB read once at the chip's path-independent
// LTS throughput cap. Measured 127.07-128.86 us across 5 runs of this exact
// structure (run-to-run LTS-cap variation, HBM 6355-6457 GB/s); best run is
// 99.8% of its achieved-bandwidth roofline (819.2 MB / 6.457 TB/s = 126.9 us).
//
// Validated design points (one bench round each):
//   - no MUFU: log(q)-log(p) via integer exponent extraction + Taylor-7
//     log1p on [-1/3,1/3]; fma/alu pipes only (rel_err ~e-7 vs 1e-3 tol).
//     This was the decisive optimization (naive logf => MUFU-bound ~1.5 ms).
//   - SPLITS=4 CTAs/row: measured optimum of drain-tail vs CTA-churn
//     (1:129.3  2:128.2  4:127.1  8:136.0 us).
//   - mask argmax(p_row)!=0  <=>  max(p_row) > p_row[0] (first-max semantics).
//   - single launch: cross-CTA row combine + global finalize via atomics that
//     self-re-arm (atomicExch) => deterministic under CUDA-graph replay.
// Tested-and-neutral (LTS cap is path-independent): cache hints, MLP batching,
// launch fusion, 128B-aligned segments. Tested-and-worse: 512-thr CTAs (reg
// occupancy), SPLITS=8 (churn).
// ============================================================================

static constexpr int VOCAB = 25000;
static constexpr int V4 = VOCAB / 4;       // 6250 float4 per row (row stride 100000 B, 16B aligned)
static constexpr int THREADS = 256;
static constexpr int SPLITS = 4;           // CTAs per row — measured optimum
static constexpr int QBASE = V4 / SPLITS;  // 1562
static constexpr int QREM  = V4 % SPLITS;  // 2 -> first 2 quarters get +1
static constexpr int MAX_ROWS = 8192;

// Per-row combine scratch + global finalize state. Zero-initialized at module
// load; every participant resets what it consumed (atomicExch), so each graph
// replay starts from the identical state.
__device__ float        g_row_sum[MAX_ROWS];
__device__ int          g_row_max[MAX_ROWS];   // int bits of positive float: order-preserving
__device__ unsigned int g_row_cnt[MAX_ROWS];
__device__ float        g_scratch = 0.0f;
__device__ unsigned int g_done    = 0u;

// log1p(f) for f in [-1/3, 1/3]:  f + f^2 * P(f), Taylor degree 7.
// Max abs error ~1.9e-5, far under the 1e-3 tolerance (measured rel_err ~e-7).
__device__ __forceinline__ float log1p_poly(float f) {
    float p = 0.142857143f;               // 1/7
    p = fmaf(p, f, -0.166666667f);        // -1/6
    p = fmaf(p, f,  0.200000000f);        //  1/5
    p = fmaf(p, f, -0.250000000f);        // -1/4
    p = fmaf(p, f,  0.333333333f);        //  1/3
    p = fmaf(p, f, -0.500000000f);        // -1/2
    return fmaf(p, f * f, f);
}

// log(q) - log(p) without MUFU: integer exponent extraction centers the
// mantissa in [2/3, 4/3) (njuffa trick); exponents combine exactly in int.
__device__ __forceinline__ float log_ratio(float q, float p) {
    int iq = __float_as_int(q), ip = __float_as_int(p);
    int eq = (iq - 0x3f2aaaab) & 0xff800000;
    int ep = (ip - 0x3f2aaaab) & 0xff800000;
    float fq = __int_as_float(iq - eq) - 1.0f;
    float fp = __int_as_float(ip - ep) - 1.0f;
    float ed = (float)(eq - ep);          // exact: multiple of 2^23, fits int32
    return fmaf(ed, 8.26295788e-8f, log1p_poly(fq) - log1p_poly(fp));   // ln2/2^23
}

__device__ __forceinline__ void accum4(const float4& pv, const float4& qv,
                                       float& acc, float& vmax) {
    acc = fmaf(qv.x, log_ratio(qv.x, pv.x), acc);
    acc = fmaf(qv.y, log_ratio(qv.y, pv.y), acc);
    acc = fmaf(qv.z, log_ratio(qv.z, pv.z), acc);
    acc = fmaf(qv.w, log_ratio(qv.w, pv.w), acc);
    vmax = fmaxf(vmax, fmaxf(fmaxf(pv.x, pv.y), fmaxf(pv.z, pv.w)));
}

__global__ void __launch_bounds__(THREADS)
kl_kernel(const float* __restrict__ p, const float* __restrict__ q,
          float* __restrict__ out, float inv_rows, unsigned int nrows) {
    const int row = blockIdx.x >> 2;
    const int qtr = blockIdx.x & 3;
    const int tid = threadIdx.x;

    // Quarter bounds: first QREM quarters take QBASE+1 float4s.
    const int qbeg = qtr * QBASE + (qtr < QREM ? qtr : QREM);
    const int qcnt = QBASE + (qtr < QREM ? 1 : 0);

    const size_t rbase = (size_t)row * VOCAB;
    const float4* p4 = reinterpret_cast<const float4*>(p + rbase) + qbeg;
    const float4* q4 = reinterpret_cast<const float4*>(q + rbase) + qbeg;

    float acc  = 0.0f;
    float vmax = 0.0f;   // inputs strictly positive; 0 bits == int 0 (scratch init)

    for (int idx = tid; idx < qcnt; idx += THREADS) {
        float4 pv = __ldcs(p4 + idx);
        float4 qv = __ldcs(q4 + idx);
        accum4(pv, qv, acc, vmax);
    }

    // intra-warp reduction
    #pragma unroll
    for (int o = 16; o; o >>= 1) {
        acc  += __shfl_xor_sync(0xffffffffu, acc, o);
        vmax  = fmaxf(vmax, __shfl_xor_sync(0xffffffffu, vmax, o));
    }

    __shared__ float s_acc[THREADS / 32];
    __shared__ float s_max[THREADS / 32];
    const int wid = tid >> 5;
    const int lid = tid & 31;
    if (lid == 0) { s_acc[wid] = acc; s_max[wid] = vmax; }
    __syncthreads();

    if (tid == 0) {
        float a = 0.0f, m = 0.0f;
        #pragma unroll
        for (int w = 0; w < THREADS / 32; w++) {
            a += s_acc[w];
            m  = fmaxf(m, s_max[w]);
        }

        // Combine the SPLITS partials for this row (mask needs full-row max).
        atomicAdd(&g_row_sum[row], a);
        atomicMax(&g_row_max[row], __float_as_int(m));  // positive floats: int order == float order
        __threadfence();
        unsigned int arrived = atomicAdd(&g_row_cnt[row], 1u);
        if (arrived == SPLITS - 1u) {
            // Last quarter to arrive finalizes the row. atomicExch reads the
            // combined values coherently from L2 AND re-arms the slots.
            float rsum = atomicExch(&g_row_sum[row], 0.0f);
            int   rmax = atomicExch(&g_row_max[row], 0);
            atomicExch(&g_row_cnt[row], 0u);

            // argmax(p_row) != 0  <=>  max(p_row) > p_row[0]
            // (argmax returns the FIRST max; a tie at index 0 means argmax==0)
            float p0 = __ldg(p + rbase);
            if (__int_as_float(rmax) > p0) atomicAdd(&g_scratch, rsum * inv_rows);

            __threadfence();
            unsigned int done = atomicAdd(&g_done, 1u);
            if (done == nrows - 1u) {
                out[0] = atomicExch(&g_scratch, 0.0f);
                atomicExch(&g_done, 0u);
            }
        }
    }
}

extern "C" void kernel_launch(void* const* d_in, const int* in_sizes, int n_in,
                              void* d_out, int out_size) {
    const float* p = (const float*)d_in[0];
    const float* q = (const float*)d_in[1];
    float* out = (float*)d_out;

    const int total = in_sizes[0];      // D0*D1*V = 102,400,000
    const int rows  = total / VOCAB;    // 4096

    kl_kernel<<<rows * SPLITS, THREADS>>>(p, q, out, 1.0f / (float)rows,
                                          (unsigned int)rows);
}